// round 4
// baseline (speedup 1.0000x reference)
#include <cuda_runtime.h>
#include <cstdint>

#define NN 100000
#define NE 1600000
#define DH 64
#define SCAN_BLK 1024
#define NB ((NN + SCAN_BLK - 1) / SCAN_BLK) // 98
#define AS_STRIDE 68

// ---------------- scratch (no allocations allowed) ----------------
__device__ float g_h1 [(size_t)NN * DH];
__device__ float g_Wt1[128 * 64];
__device__ float g_Wt2[128 * 64];
__device__ int   g_esrc[NE];      // src ids grouped by dst (CSR)
__device__ int   g_cnt[NN];
__device__ int   g_offs[NN + 1];
__device__ int   g_cursor[NN];
__device__ int   g_bsum[NB];
__device__ int   g_is64;

// ---------------- dtype detection: int64 vs int32 edge_index --------------
__global__ void detect_idx(const void* __restrict__ ei) {
    if (threadIdx.x == 0 && blockIdx.x == 0) {
        const long long* p = (const long long*)ei;
        bool all64 = true;
        #pragma unroll
        for (int i = 0; i < 8; ++i) {
            long long v = p[i];
            if (v < 0 || v >= NN) all64 = false;
        }
        g_is64 = all64 ? 1 : 0;
    }
}

// ---------------- CSR build ----------------
__global__ void zero_int(int* __restrict__ p, int n) {
    int i = blockIdx.x * blockDim.x + threadIdx.x;
    if (i < n) p[i] = 0;
}

__global__ void hist_dst(const void* __restrict__ ei, int* __restrict__ cnt) {
    int i = blockIdx.x * blockDim.x + threadIdx.x;
    if (i >= NE) return;
    int d = g_is64 ? (int)((const long long*)ei)[NE + i]
                   : ((const int*)ei)[NE + i];
    atomicAdd(&cnt[d], 1);
}

// per-block exclusive scan: 256 threads x 4 counts = 1024/block
__global__ void scan_blocks(const int* __restrict__ cnt,
                            int* __restrict__ offs, int* __restrict__ bsum) {
    __shared__ int sh[256];
    int t = threadIdx.x;
    int base = blockIdx.x * SCAN_BLK + t * 4;
    int c0 = (base + 0 < NN) ? cnt[base + 0] : 0;
    int c1 = (base + 1 < NN) ? cnt[base + 1] : 0;
    int c2 = (base + 2 < NN) ? cnt[base + 2] : 0;
    int c3 = (base + 3 < NN) ? cnt[base + 3] : 0;
    int s = c0 + c1 + c2 + c3;
    sh[t] = s;
    __syncthreads();
    #pragma unroll
    for (int off = 1; off < 256; off <<= 1) {
        int v = (t >= off) ? sh[t - off] : 0;
        __syncthreads();
        sh[t] += v;
        __syncthreads();
    }
    int excl = sh[t] - s;
    if (t == 255) bsum[blockIdx.x] = sh[255];
    if (base + 0 < NN) offs[base + 0] = excl;  excl += c0;
    if (base + 1 < NN) offs[base + 1] = excl;  excl += c1;
    if (base + 2 < NN) offs[base + 2] = excl;  excl += c2;
    if (base + 3 < NN) offs[base + 3] = excl;
}

__global__ void scan_bsums(int* __restrict__ bsum) {
    if (threadIdx.x == 0 && blockIdx.x == 0) {
        int run = 0;
        for (int b = 0; b < NB; ++b) { int t = bsum[b]; bsum[b] = run; run += t; }
    }
}

__global__ void add_base(int* __restrict__ offs, const int* __restrict__ bsum,
                         int* __restrict__ cursor) {
    int i = blockIdx.x * blockDim.x + threadIdx.x;
    if (i < NN) {
        int v = offs[i] + bsum[i / SCAN_BLK];
        offs[i] = v;
        cursor[i] = v;
    }
    if (i == 0) offs[NN] = NE;
}

__global__ void place_edges(const void* __restrict__ ei,
                            int* __restrict__ cursor, int* __restrict__ esrc) {
    int i = blockIdx.x * blockDim.x + threadIdx.x;
    if (i >= NE) return;
    int s, d;
    if (g_is64) {
        const long long* p = (const long long*)ei;
        s = (int)p[i];  d = (int)p[NE + i];
    } else {
        const int* p = (const int*)ei;
        s = p[i];       d = p[NE + i];
    }
    int pos = atomicAdd(&cursor[d], 1);
    esrc[pos] = s;
}

// ---------------- tiny prep: Wt[k][n] = k<64 ? Wrel[n][k] : Wroot[n][k-64] ----
__global__ void prep_w(const float* __restrict__ Wrel,
                       const float* __restrict__ Wroot,
                       float* __restrict__ Wt) {
    int i = blockIdx.x * blockDim.x + threadIdx.x;
    if (i < 128 * 64) {
        int k = i >> 6;
        int n = i & 63;
        Wt[i] = (k < 64) ? Wrel[n * 64 + k] : Wroot[n * 64 + (k - 64)];
    }
}

// ---------------- fused layer: gather + dual-GEMM (+ optional head) ----------
// Block: 128 nodes, 256 threads.
//   Phase G: 8 warps gather neighbor sums directly into As (smem).
//   Phase M: ch0 = As(agg) x Wt[0:64], restage As with xin, ch1 x Wt[64:128].
//   Epilogue: bias+relu -> out[NN,64]; FINAL: relu tile -> smem, 3-dim head -> out[NN,3].
template<bool FINAL>
__global__ void __launch_bounds__(256, 3)
layer_fused(const float* __restrict__ xin,   // [NN,64]
            const int*   __restrict__ offs,
            const int*   __restrict__ esrc,
            const float* __restrict__ Wt,    // [128,64] k-major
            const float* __restrict__ bias,  // [64]
            const float* __restrict__ Wlin,  // [3,64]  (FINAL only)
            const float* __restrict__ blin,  // [3]     (FINAL only)
            float* __restrict__ out) {       // [NN,64] or [NN,3]
    extern __shared__ float sm[];
    float* Bs = sm;                      // [128][64]
    float* As = sm + 128 * 64;           // [128][AS_STRIDE]
    float* Wl = As + 128 * AS_STRIDE;    // [192] (FINAL)

    const int tid  = threadIdx.x;
    const int lane = tid & 31;
    const int warp = tid >> 5;           // 0..7
    const int tn   = tid & 7;            // 0..7
    const int tm   = tid >> 3;           // 0..31
    const int m0   = blockIdx.x * 128;

    // load weight tile (2048 float4 / 256 threads = 8 each)
    #pragma unroll
    for (int i = tid; i < 128 * 64 / 4; i += 256)
        reinterpret_cast<float4*>(Bs)[i] = reinterpret_cast<const float4*>(Wt)[i];
    if (FINAL && tid < 192) Wl[tid] = Wlin[tid];

    // ---- Phase G: gather agg rows into As ----
    const float2* f2 = reinterpret_cast<const float2*>(xin);
    #pragma unroll 1
    for (int i = 0; i < 16; ++i) {
        int m  = warp * 16 + i;
        int gm = m0 + m;
        float sx = 0.f, sy = 0.f;
        if (gm < NN) {
            int s0 = offs[gm];
            int s1 = offs[gm + 1];
            int j = s0;
            for (; j + 4 <= s1; j += 4) {
                int a = esrc[j], b = esrc[j + 1], c = esrc[j + 2], d = esrc[j + 3];
                float2 v0 = f2[(size_t)a * 32 + lane];
                float2 v1 = f2[(size_t)b * 32 + lane];
                float2 v2 = f2[(size_t)c * 32 + lane];
                float2 v3 = f2[(size_t)d * 32 + lane];
                sx += v0.x + v1.x + v2.x + v3.x;
                sy += v0.y + v1.y + v2.y + v3.y;
            }
            for (; j < s1; ++j) {
                float2 v = f2[(size_t)esrc[j] * 32 + lane];
                sx += v.x; sy += v.y;
            }
        }
        *reinterpret_cast<float2*>(As + m * AS_STRIDE + lane * 2) = make_float2(sx, sy);
    }

    float acc[4][8];
    #pragma unroll
    for (int i = 0; i < 4; ++i)
        #pragma unroll
        for (int j = 0; j < 8; ++j) acc[i][j] = 0.f;

    // ---- Phase M ----
    #pragma unroll
    for (int ch = 0; ch < 2; ++ch) {
        if (ch == 1) {
            __syncthreads();   // everyone done reading ch0 As
            // restage As with xin rows (2048 float4 slots / 256 = 8 each)
            #pragma unroll
            for (int r = 0; r < 8; ++r) {
                int idx = r * 256 + tid;
                int m   = idx >> 4;
                int q   = idx & 15;
                int gm  = m0 + m;
                float4 v = (gm < NN)
                    ? *reinterpret_cast<const float4*>(xin + (size_t)gm * DH + q * 4)
                    : make_float4(0.f, 0.f, 0.f, 0.f);
                *reinterpret_cast<float4*>(As + m * AS_STRIDE + q * 4) = v;
            }
        }
        __syncthreads();

        const float* Bc = Bs + ch * 64 * 64;
        #pragma unroll 4
        for (int k = 0; k < 64; ++k) {
            const float* brow = Bc + k * 64 + tn * 8;
            float4 b0 = *reinterpret_cast<const float4*>(brow);
            float4 b1 = *reinterpret_cast<const float4*>(brow + 4);
            #pragma unroll
            for (int i = 0; i < 4; ++i) {
                float a = As[(tm + 32 * i) * AS_STRIDE + k];
                acc[i][0] += a * b0.x;  acc[i][1] += a * b0.y;
                acc[i][2] += a * b0.z;  acc[i][3] += a * b0.w;
                acc[i][4] += a * b1.x;  acc[i][5] += a * b1.y;
                acc[i][6] += a * b1.z;  acc[i][7] += a * b1.w;
            }
        }
    }

    // ---- Epilogue ----
    float4 bb0 = *reinterpret_cast<const float4*>(bias + tn * 8);
    float4 bb1 = *reinterpret_cast<const float4*>(bias + tn * 8 + 4);

    if (!FINAL) {
        #pragma unroll
        for (int i = 0; i < 4; ++i) {
            int gm = m0 + tm + 32 * i;
            if (gm < NN) {
                float4 o0, o1;
                o0.x = fmaxf(acc[i][0] + bb0.x, 0.f);
                o0.y = fmaxf(acc[i][1] + bb0.y, 0.f);
                o0.z = fmaxf(acc[i][2] + bb0.z, 0.f);
                o0.w = fmaxf(acc[i][3] + bb0.w, 0.f);
                o1.x = fmaxf(acc[i][4] + bb1.x, 0.f);
                o1.y = fmaxf(acc[i][5] + bb1.y, 0.f);
                o1.z = fmaxf(acc[i][6] + bb1.z, 0.f);
                o1.w = fmaxf(acc[i][7] + bb1.w, 0.f);
                float* po = out + (size_t)gm * DH + tn * 8;
                *reinterpret_cast<float4*>(po)     = o0;
                *reinterpret_cast<float4*>(po + 4) = o1;
            }
        }
    } else {
        __syncthreads();   // all k-loop reads of As done before overwrite
        #pragma unroll
        for (int i = 0; i < 4; ++i) {
            float* row = As + (tm + 32 * i) * AS_STRIDE + tn * 8;
            row[0] = fmaxf(acc[i][0] + bb0.x, 0.f);
            row[1] = fmaxf(acc[i][1] + bb0.y, 0.f);
            row[2] = fmaxf(acc[i][2] + bb0.z, 0.f);
            row[3] = fmaxf(acc[i][3] + bb0.w, 0.f);
            row[4] = fmaxf(acc[i][4] + bb1.x, 0.f);
            row[5] = fmaxf(acc[i][5] + bb1.y, 0.f);
            row[6] = fmaxf(acc[i][6] + bb1.z, 0.f);
            row[7] = fmaxf(acc[i][7] + bb1.w, 0.f);
        }
        __syncthreads();
        // head: 128 nodes x 3 outputs = 384 dots of length 64
        #pragma unroll
        for (int r = 0; r < 2; ++r) {
            int idx = tid + 256 * r;
            if (idx < 384) {
                int m = idx / 3;
                int o = idx - 3 * m;
                int gm = m0 + m;
                if (gm < NN) {
                    float s = blin[o];
                    const float* hrow = As + m * AS_STRIDE;
                    const float* wrow = Wl + o * 64;
                    #pragma unroll 16
                    for (int k = 0; k < 64; ++k) s += hrow[k] * wrow[k];
                    out[(size_t)gm * 3 + o] = s;
                }
            }
        }
    }
}

// ---------------- launch ----------------
extern "C" void kernel_launch(void* const* d_in, const int* in_sizes, int n_in,
                              void* d_out, int out_size) {
    const float* x      = (const float*)d_in[0];
    const void*  ei     = d_in[1];
    const float* W1_rel = (const float*)d_in[2];
    const float* b1     = (const float*)d_in[3];
    const float* W1_rt  = (const float*)d_in[4];
    const float* W2_rel = (const float*)d_in[5];
    const float* b2     = (const float*)d_in[6];
    const float* W2_rt  = (const float*)d_in[7];
    const float* W_lin  = (const float*)d_in[8];
    const float* b_lin  = (const float*)d_in[9];
    float*       out    = (float*)d_out;

    float *h1, *Wt1, *Wt2;
    int *esrc, *cnt, *offs, *cursor, *bsum;
    cudaGetSymbolAddress((void**)&h1,     g_h1);
    cudaGetSymbolAddress((void**)&Wt1,    g_Wt1);
    cudaGetSymbolAddress((void**)&Wt2,    g_Wt2);
    cudaGetSymbolAddress((void**)&esrc,   g_esrc);
    cudaGetSymbolAddress((void**)&cnt,    g_cnt);
    cudaGetSymbolAddress((void**)&offs,   g_offs);
    cudaGetSymbolAddress((void**)&cursor, g_cursor);
    cudaGetSymbolAddress((void**)&bsum,   g_bsum);

    const int smem = (128 * 64 + 128 * AS_STRIDE + 192) * sizeof(float); // 68352 B
    cudaFuncSetAttribute(layer_fused<false>, cudaFuncAttributeMaxDynamicSharedMemorySize, smem);
    cudaFuncSetAttribute(layer_fused<true>,  cudaFuncAttributeMaxDynamicSharedMemorySize, smem);

    const int egrid = (NE + 255) / 256;
    const int ngrid = (NN + 255) / 256;
    const int lgrid = (NN + 127) / 128;

    // index ingest + CSR build (once per launch)
    detect_idx<<<1, 32>>>(ei);
    zero_int<<<ngrid, 256>>>(cnt, NN);
    hist_dst<<<egrid, 256>>>(ei, cnt);
    scan_blocks<<<NB, 256>>>(cnt, offs, bsum);
    scan_bsums<<<1, 32>>>(bsum);
    add_base<<<ngrid, 256>>>(offs, bsum, cursor);
    place_edges<<<egrid, 256>>>(ei, cursor, esrc);

    // weights prep
    prep_w<<<32, 256>>>(W1_rel, W1_rt, Wt1);
    prep_w<<<32, 256>>>(W2_rel, W2_rt, Wt2);

    // fused layers
    layer_fused<false><<<lgrid, 256, smem>>>(x,  offs, esrc, Wt1, b1, nullptr, nullptr, h1);
    layer_fused<true ><<<lgrid, 256, smem>>>(h1, offs, esrc, Wt2, b2, W_lin,  b_lin,  out);
}

// round 5
// speedup vs baseline: 1.3243x; 1.3243x over previous
#include <cuda_runtime.h>
#include <cstdint>

#define NN 100000
#define NE 1600000
#define DH 64
#define SCAN_BLK 1024
#define NB ((NN + SCAN_BLK - 1) / SCAN_BLK) // 98
#define AS_STRIDE 68
#define BS_STRIDE 130

// ---------------- scratch (no allocations allowed) ----------------
__device__ float g_agg[(size_t)NN * DH];
__device__ float g_h1 [(size_t)NN * DH];
__device__ float g_h2 [(size_t)NN * DH];
__device__ float g_Wn1[64 * BS_STRIDE];   // [n][k] n-major, k = rel(0:64)|root(64:128), pad 130
__device__ float g_Wn2[64 * BS_STRIDE];
__device__ int   g_esrc[NE];
__device__ int   g_cnt[NN];
__device__ int   g_offs[NN + 1];
__device__ int   g_cursor[NN];
__device__ int   g_bsum[NB];
__device__ int   g_is64;

// ---------------- dtype detection: int64 vs int32 edge_index --------------
__global__ void detect_idx(const void* __restrict__ ei) {
    if (threadIdx.x == 0 && blockIdx.x == 0) {
        const long long* p = (const long long*)ei;
        bool all64 = true;
        #pragma unroll
        for (int i = 0; i < 8; ++i) {
            long long v = p[i];
            if (v < 0 || v >= NN) all64 = false;
        }
        g_is64 = all64 ? 1 : 0;
    }
}

// ---------------- CSR build ----------------
__global__ void zero_int(int* __restrict__ p, int n) {
    int i = blockIdx.x * blockDim.x + threadIdx.x;
    if (i < n) p[i] = 0;
}

// 4 edges per thread (NE % 4 == 0)
__global__ void hist_dst(const void* __restrict__ ei, int* __restrict__ cnt) {
    int i = (blockIdx.x * blockDim.x + threadIdx.x) * 4;
    if (i >= NE) return;
    int d0, d1, d2, d3;
    if (g_is64) {
        longlong4 q = *reinterpret_cast<const longlong4*>((const long long*)ei + NE + i);
        d0 = (int)q.x; d1 = (int)q.y; d2 = (int)q.z; d3 = (int)q.w;
    } else {
        int4 q = *reinterpret_cast<const int4*>((const int*)ei + NE + i);
        d0 = q.x; d1 = q.y; d2 = q.z; d3 = q.w;
    }
    atomicAdd(&cnt[d0], 1);
    atomicAdd(&cnt[d1], 1);
    atomicAdd(&cnt[d2], 1);
    atomicAdd(&cnt[d3], 1);
}

// per-block exclusive scan: 256 threads x 4 counts = 1024/block
__global__ void scan_blocks(const int* __restrict__ cnt,
                            int* __restrict__ offs, int* __restrict__ bsum) {
    __shared__ int sh[256];
    int t = threadIdx.x;
    int base = blockIdx.x * SCAN_BLK + t * 4;
    int c0 = (base + 0 < NN) ? cnt[base + 0] : 0;
    int c1 = (base + 1 < NN) ? cnt[base + 1] : 0;
    int c2 = (base + 2 < NN) ? cnt[base + 2] : 0;
    int c3 = (base + 3 < NN) ? cnt[base + 3] : 0;
    int s = c0 + c1 + c2 + c3;
    sh[t] = s;
    __syncthreads();
    #pragma unroll
    for (int off = 1; off < 256; off <<= 1) {
        int v = (t >= off) ? sh[t - off] : 0;
        __syncthreads();
        sh[t] += v;
        __syncthreads();
    }
    int excl = sh[t] - s;
    if (t == 255) bsum[blockIdx.x] = sh[255];
    if (base + 0 < NN) offs[base + 0] = excl;  excl += c0;
    if (base + 1 < NN) offs[base + 1] = excl;  excl += c1;
    if (base + 2 < NN) offs[base + 2] = excl;  excl += c2;
    if (base + 3 < NN) offs[base + 3] = excl;
}

// parallel scan of the 98 block sums (1 block, 128 threads)
__global__ void scan_bsums(int* __restrict__ bsum) {
    __shared__ int sh[128];
    int t = threadIdx.x;
    int v = (t < NB) ? bsum[t] : 0;
    sh[t] = v;
    __syncthreads();
    #pragma unroll
    for (int off = 1; off < 128; off <<= 1) {
        int u = (t >= off) ? sh[t - off] : 0;
        __syncthreads();
        sh[t] += u;
        __syncthreads();
    }
    if (t < NB) bsum[t] = sh[t] - v;   // exclusive
}

__global__ void add_base(int* __restrict__ offs, const int* __restrict__ bsum,
                         int* __restrict__ cursor) {
    int i = blockIdx.x * blockDim.x + threadIdx.x;
    if (i < NN) {
        int v = offs[i] + bsum[i / SCAN_BLK];
        offs[i] = v;
        cursor[i] = v;
    }
    if (i == 0) offs[NN] = NE;
}

// 4 edges per thread
__global__ void place_edges(const void* __restrict__ ei,
                            int* __restrict__ cursor, int* __restrict__ esrc) {
    int i = (blockIdx.x * blockDim.x + threadIdx.x) * 4;
    if (i >= NE) return;
    int s0, s1, s2, s3, d0, d1, d2, d3;
    if (g_is64) {
        const long long* p = (const long long*)ei;
        longlong4 qs = *reinterpret_cast<const longlong4*>(p + i);
        longlong4 qd = *reinterpret_cast<const longlong4*>(p + NE + i);
        s0 = (int)qs.x; s1 = (int)qs.y; s2 = (int)qs.z; s3 = (int)qs.w;
        d0 = (int)qd.x; d1 = (int)qd.y; d2 = (int)qd.z; d3 = (int)qd.w;
    } else {
        const int* p = (const int*)ei;
        int4 qs = *reinterpret_cast<const int4*>(p + i);
        int4 qd = *reinterpret_cast<const int4*>(p + NE + i);
        s0 = qs.x; s1 = qs.y; s2 = qs.z; s3 = qs.w;
        d0 = qd.x; d1 = qd.y; d2 = qd.z; d3 = qd.w;
    }
    esrc[atomicAdd(&cursor[d0], 1)] = s0;
    esrc[atomicAdd(&cursor[d1], 1)] = s1;
    esrc[atomicAdd(&cursor[d2], 1)] = s2;
    esrc[atomicAdd(&cursor[d3], 1)] = s3;
}

// ---------------- prep: Wn[n][k] = k<64 ? Wrel[n][k] : Wroot[n][k-64] (pad 130) ----
__global__ void prep_w(const float* __restrict__ Wrel,
                       const float* __restrict__ Wroot,
                       float* __restrict__ Wn) {
    int i = blockIdx.x * blockDim.x + threadIdx.x;   // 0..8319
    if (i < 64 * BS_STRIDE) {
        int n = i / BS_STRIDE;
        int k = i - n * BS_STRIDE;
        float v = 0.f;
        if (k < 64)       v = Wrel [n * 64 + k];
        else if (k < 128) v = Wroot[n * 64 + (k - 64)];
        Wn[i] = v;
    }
}

// ---------------- gather aggregation (R3, unchanged) ----------------
__global__ void __launch_bounds__(256)
gather_agg(const float* __restrict__ feat,
           const int* __restrict__ offs,
           const int* __restrict__ esrc,
           float* __restrict__ agg) {
    int node = blockIdx.x * (blockDim.x >> 5) + (threadIdx.x >> 5);
    if (node >= NN) return;
    int lane = threadIdx.x & 31;
    int s0 = offs[node];
    int s1 = offs[node + 1];
    const float2* f2 = reinterpret_cast<const float2*>(feat);
    float sx = 0.f, sy = 0.f;
    int j = s0;
    for (; j + 4 <= s1; j += 4) {
        int a = esrc[j], b = esrc[j + 1], c = esrc[j + 2], d = esrc[j + 3];
        float2 v0 = f2[(size_t)a * 32 + lane];
        float2 v1 = f2[(size_t)b * 32 + lane];
        float2 v2 = f2[(size_t)c * 32 + lane];
        float2 v3 = f2[(size_t)d * 32 + lane];
        sx += v0.x + v1.x + v2.x + v3.x;
        sy += v0.y + v1.y + v2.y + v3.y;
    }
    for (; j < s1; ++j) {
        float2 v = f2[(size_t)esrc[j] * 32 + lane];
        sx += v.x; sy += v.y;
    }
    reinterpret_cast<float2*>(agg)[(size_t)node * 32 + lane] = make_float2(sx, sy);
}

// ---------------- fused dual-GEMM with packed f32x2, K-packed ----------------
// out[m][n] = relu( agg[m][:] . Wn[n][0:64] + xin[m][:] . Wn[n][64:128] + bias[n] )
// 128 threads, block tile 128m x 64n, 8x8 micro. Acc holds (even-k, odd-k) partials.
__global__ void __launch_bounds__(128)
gemm_fused(const float* __restrict__ A0,   // agg [NN,64]
           const float* __restrict__ A1,   // xin [NN,64]
           const float* __restrict__ Wn,   // [64][130] n-major
           const float* __restrict__ bias, // [64]
           float* __restrict__ out) {      // [NN,64]
    extern __shared__ float sm[];
    float* Bs = sm;                        // [64][130] = 8320 floats
    float* As = sm + 64 * BS_STRIDE;       // [128][68] = 8704 floats

    const int tid = threadIdx.x;
    const int tn  = tid & 7;               // n-lane: columns {j*8+tn}
    const int tm  = tid >> 3;              // 0..15: rows {tm+16i}
    const int m0  = blockIdx.x * 128;

    // copy Wn -> Bs (identity, float2, conflict-free)
    for (int i = tid; i < 64 * BS_STRIDE / 2; i += 128)
        reinterpret_cast<float2*>(Bs)[i] = reinterpret_cast<const float2*>(Wn)[i];

    unsigned long long acc2[8][8];
    #pragma unroll
    for (int i = 0; i < 8; ++i)
        #pragma unroll
        for (int j = 0; j < 8; ++j) acc2[i][j] = 0ull;

    #pragma unroll
    for (int ch = 0; ch < 2; ++ch) {
        const float* A = ch ? A1 : A0;
        __syncthreads();   // Bs ready on first pass; As reads done before restage
        // stage As[m][0:64] for this chunk (coalesced float4)
        #pragma unroll
        for (int r = 0; r < 16; ++r) {
            int idx = r * 128 + tid;
            int m   = idx >> 4;
            int q   = idx & 15;
            int gm  = m0 + m;
            float4 v = (gm < NN)
                ? *reinterpret_cast<const float4*>(A + (size_t)gm * DH + q * 4)
                : make_float4(0.f, 0.f, 0.f, 0.f);
            *reinterpret_cast<float4*>(As + m * AS_STRIDE + q * 4) = v;
        }
        __syncthreads();

        const float* Bc = Bs + ch * 64;    // k-half offset within each n row
        #pragma unroll 2
        for (int kp = 0; kp < 32; ++kp) {
            unsigned long long b2[8];
            #pragma unroll
            for (int j = 0; j < 8; ++j)
                b2[j] = *reinterpret_cast<const unsigned long long*>(
                            Bc + (j * 8 + tn) * BS_STRIDE + 2 * kp);
            #pragma unroll
            for (int i = 0; i < 8; ++i) {
                unsigned long long a2 = *reinterpret_cast<const unsigned long long*>(
                            As + (tm + 16 * i) * AS_STRIDE + 2 * kp);
                #pragma unroll
                for (int j = 0; j < 8; ++j) {
                    asm("fma.rn.f32x2 %0, %1, %2, %0;"
                        : "+l"(acc2[i][j]) : "l"(a2), "l"(b2[j]));
                }
            }
        }
    }

    // epilogue: fold halves, +bias, relu, store (STG.32, 4 sectors/warp-store)
    float bb[8];
    #pragma unroll
    for (int j = 0; j < 8; ++j) bb[j] = bias[j * 8 + tn];
    #pragma unroll
    for (int i = 0; i < 8; ++i) {
        int gm = m0 + tm + 16 * i;
        if (gm < NN) {
            #pragma unroll
            for (int j = 0; j < 8; ++j) {
                unsigned long long a = acc2[i][j];
                float lo = __uint_as_float((unsigned)(a & 0xffffffffull));
                float hi = __uint_as_float((unsigned)(a >> 32));
                out[(size_t)gm * DH + j * 8 + tn] = fmaxf(lo + hi + bb[j], 0.f);
            }
        }
    }
}

// ---------------- final head ----------------
__global__ void final_lin(const float* __restrict__ h,
                          const float* __restrict__ W,   // [3,64]
                          const float* __restrict__ b,   // [3]
                          float* __restrict__ out) {     // [NN,3]
    __shared__ float Ws[3 * 64];
    __shared__ float hs[64 * 64];
    int tid = threadIdx.x;     // 256
    if (tid < 192) Ws[tid] = W[tid];
    int n0 = blockIdx.x * 64;
    #pragma unroll
    for (int r = 0; r < 4; ++r) {
        int idx = r * 256 + tid;
        int m = idx >> 4, q = idx & 15;
        int gm = n0 + m;
        float4 v = (gm < NN)
            ? reinterpret_cast<const float4*>(h + (size_t)gm * DH)[q]
            : make_float4(0.f, 0.f, 0.f, 0.f);
        reinterpret_cast<float4*>(hs)[idx] = v;
    }
    __syncthreads();
    if (tid < 192) {
        int m = tid / 3;
        int o = tid - 3 * m;
        int gm = n0 + m;
        if (gm < NN) {
            float s = b[o];
            #pragma unroll 16
            for (int k = 0; k < 64; ++k) s += hs[m * 64 + k] * Ws[o * 64 + k];
            out[(size_t)gm * 3 + o] = s;
        }
    }
}

// ---------------- launch ----------------
extern "C" void kernel_launch(void* const* d_in, const int* in_sizes, int n_in,
                              void* d_out, int out_size) {
    const float* x      = (const float*)d_in[0];
    const void*  ei     = d_in[1];
    const float* W1_rel = (const float*)d_in[2];
    const float* b1     = (const float*)d_in[3];
    const float* W1_rt  = (const float*)d_in[4];
    const float* W2_rel = (const float*)d_in[5];
    const float* b2     = (const float*)d_in[6];
    const float* W2_rt  = (const float*)d_in[7];
    const float* W_lin  = (const float*)d_in[8];
    const float* b_lin  = (const float*)d_in[9];
    float*       out    = (float*)d_out;

    float *agg, *h1, *h2, *Wn1, *Wn2;
    int *esrc, *cnt, *offs, *cursor, *bsum;
    cudaGetSymbolAddress((void**)&agg,    g_agg);
    cudaGetSymbolAddress((void**)&h1,     g_h1);
    cudaGetSymbolAddress((void**)&h2,     g_h2);
    cudaGetSymbolAddress((void**)&Wn1,    g_Wn1);
    cudaGetSymbolAddress((void**)&Wn2,    g_Wn2);
    cudaGetSymbolAddress((void**)&esrc,   g_esrc);
    cudaGetSymbolAddress((void**)&cnt,    g_cnt);
    cudaGetSymbolAddress((void**)&offs,   g_offs);
    cudaGetSymbolAddress((void**)&cursor, g_cursor);
    cudaGetSymbolAddress((void**)&bsum,   g_bsum);

    const int smem = (64 * BS_STRIDE + 128 * AS_STRIDE) * sizeof(float);  // 68096 B
    cudaFuncSetAttribute(gemm_fused, cudaFuncAttributeMaxDynamicSharedMemorySize, smem);

    const int e4grid = (NE / 4 + 255) / 256;
    const int ngrid  = (NN + 255) / 256;
    const int ggrid  = (NN + 127) / 128;
    const int fgrid  = (NN + 63) / 64;
    const int agrid  = (NN + 7) / 8;

    // index ingest + CSR build
    detect_idx<<<1, 32>>>(ei);
    zero_int<<<ngrid, 256>>>(cnt, NN);
    hist_dst<<<e4grid, 256>>>(ei, cnt);
    scan_blocks<<<NB, 256>>>(cnt, offs, bsum);
    scan_bsums<<<1, 128>>>(bsum);
    add_base<<<ngrid, 256>>>(offs, bsum, cursor);
    place_edges<<<e4grid, 256>>>(ei, cursor, esrc);

    // weights prep
    prep_w<<<(64 * BS_STRIDE + 255) / 256, 256>>>(W1_rel, W1_rt, Wn1);
    prep_w<<<(64 * BS_STRIDE + 255) / 256, 256>>>(W2_rel, W2_rt, Wn2);

    // layer 1
    gather_agg<<<agrid, 256>>>(x, offs, esrc, agg);
    gemm_fused<<<ggrid, 128, smem>>>(agg, x, Wn1, b1, h1);

    // layer 2
    gather_agg<<<agrid, 256>>>(h1, offs, esrc, agg);
    gemm_fused<<<ggrid, 128, smem>>>(agg, h1, Wn2, b2, h2);

    // head
    final_lin<<<fgrid, 256>>>(h2, W_lin, b_lin, out);
}

// round 6
// speedup vs baseline: 1.7237x; 1.3017x over previous
#include <cuda_runtime.h>
#include <cstdint>

#define NN 100000
#define NE 1600000
#define DH 64
#define SCAN_BLK 1024
#define NB ((NN + SCAN_BLK - 1) / SCAN_BLK) // 98
#define AS_STRIDE 68
#define WS_STRIDE 132

// ---------------- scratch (no allocations allowed) ----------------
__device__ float g_agg[(size_t)NN * DH];
__device__ float g_h1 [(size_t)NN * DH];
__device__ float g_Wn1[64 * WS_STRIDE];   // [n][k] tf32-rounded, k = rel(0:64)|root(64:128)
__device__ float g_Wn2[64 * WS_STRIDE];
__device__ int   g_esrc[NE];
__device__ int   g_cnt[NN];
__device__ int   g_offs[NN + 1];
__device__ int   g_cursor[NN];
__device__ int   g_bsum[NB];
__device__ int   g_is64;

__device__ __forceinline__ float to_tf32(float x) {
    unsigned u;
    asm("cvt.rna.tf32.f32 %0, %1;" : "=r"(u) : "f"(x));
    return __uint_as_float(u);
}

__device__ __forceinline__ void mma_tf32(float c[4], const unsigned a[4], const unsigned b[2]) {
    asm("mma.sync.aligned.m16n8k8.row.col.f32.tf32.tf32.f32 "
        "{%0,%1,%2,%3}, {%4,%5,%6,%7}, {%8,%9}, {%0,%1,%2,%3};"
        : "+f"(c[0]), "+f"(c[1]), "+f"(c[2]), "+f"(c[3])
        : "r"(a[0]), "r"(a[1]), "r"(a[2]), "r"(a[3]), "r"(b[0]), "r"(b[1]));
}

// ---------------- zero cnt + detect edge_index dtype ----------------
__global__ void zero_detect(const void* __restrict__ ei, int* __restrict__ cnt) {
    int i = blockIdx.x * blockDim.x + threadIdx.x;
    if (i < NN) cnt[i] = 0;
    if (i == 0) {
        const long long* p = (const long long*)ei;
        bool all64 = true;
        #pragma unroll
        for (int j = 0; j < 8; ++j) {
            long long v = p[j];
            if (v < 0 || v >= NN) all64 = false;
        }
        g_is64 = all64 ? 1 : 0;
    }
}

// ---------------- CSR build (R5, 4 edges/thread) ----------------
__global__ void hist_dst(const void* __restrict__ ei, int* __restrict__ cnt) {
    int i = (blockIdx.x * blockDim.x + threadIdx.x) * 4;
    if (i >= NE) return;
    int d0, d1, d2, d3;
    if (g_is64) {
        longlong4 q = *reinterpret_cast<const longlong4*>((const long long*)ei + NE + i);
        d0 = (int)q.x; d1 = (int)q.y; d2 = (int)q.z; d3 = (int)q.w;
    } else {
        int4 q = *reinterpret_cast<const int4*>((const int*)ei + NE + i);
        d0 = q.x; d1 = q.y; d2 = q.z; d3 = q.w;
    }
    atomicAdd(&cnt[d0], 1);
    atomicAdd(&cnt[d1], 1);
    atomicAdd(&cnt[d2], 1);
    atomicAdd(&cnt[d3], 1);
}

__global__ void scan_blocks(const int* __restrict__ cnt,
                            int* __restrict__ offs, int* __restrict__ bsum) {
    __shared__ int sh[256];
    int t = threadIdx.x;
    int base = blockIdx.x * SCAN_BLK + t * 4;
    int c0 = (base + 0 < NN) ? cnt[base + 0] : 0;
    int c1 = (base + 1 < NN) ? cnt[base + 1] : 0;
    int c2 = (base + 2 < NN) ? cnt[base + 2] : 0;
    int c3 = (base + 3 < NN) ? cnt[base + 3] : 0;
    int s = c0 + c1 + c2 + c3;
    sh[t] = s;
    __syncthreads();
    #pragma unroll
    for (int off = 1; off < 256; off <<= 1) {
        int v = (t >= off) ? sh[t - off] : 0;
        __syncthreads();
        sh[t] += v;
        __syncthreads();
    }
    int excl = sh[t] - s;
    if (t == 255) bsum[blockIdx.x] = sh[255];
    if (base + 0 < NN) offs[base + 0] = excl;  excl += c0;
    if (base + 1 < NN) offs[base + 1] = excl;  excl += c1;
    if (base + 2 < NN) offs[base + 2] = excl;  excl += c2;
    if (base + 3 < NN) offs[base + 3] = excl;
}

__global__ void scan_bsums(int* __restrict__ bsum) {
    __shared__ int sh[128];
    int t = threadIdx.x;
    int v = (t < NB) ? bsum[t] : 0;
    sh[t] = v;
    __syncthreads();
    #pragma unroll
    for (int off = 1; off < 128; off <<= 1) {
        int u = (t >= off) ? sh[t - off] : 0;
        __syncthreads();
        sh[t] += u;
        __syncthreads();
    }
    if (t < NB) bsum[t] = sh[t] - v;
}

__global__ void add_base(int* __restrict__ offs, const int* __restrict__ bsum,
                         int* __restrict__ cursor) {
    int i = blockIdx.x * blockDim.x + threadIdx.x;
    if (i < NN) {
        int v = offs[i] + bsum[i / SCAN_BLK];
        offs[i] = v;
        cursor[i] = v;
    }
    if (i == 0) offs[NN] = NE;
}

__global__ void place_edges(const void* __restrict__ ei,
                            int* __restrict__ cursor, int* __restrict__ esrc) {
    int i = (blockIdx.x * blockDim.x + threadIdx.x) * 4;
    if (i >= NE) return;
    int s0, s1, s2, s3, d0, d1, d2, d3;
    if (g_is64) {
        const long long* p = (const long long*)ei;
        longlong4 qs = *reinterpret_cast<const longlong4*>(p + i);
        longlong4 qd = *reinterpret_cast<const longlong4*>(p + NE + i);
        s0 = (int)qs.x; s1 = (int)qs.y; s2 = (int)qs.z; s3 = (int)qs.w;
        d0 = (int)qd.x; d1 = (int)qd.y; d2 = (int)qd.z; d3 = (int)qd.w;
    } else {
        const int* p = (const int*)ei;
        int4 qs = *reinterpret_cast<const int4*>(p + i);
        int4 qd = *reinterpret_cast<const int4*>(p + NE + i);
        s0 = qs.x; s1 = qs.y; s2 = qs.z; s3 = qs.w;
        d0 = qd.x; d1 = qd.y; d2 = qd.z; d3 = qd.w;
    }
    esrc[atomicAdd(&cursor[d0], 1)] = s0;
    esrc[atomicAdd(&cursor[d1], 1)] = s1;
    esrc[atomicAdd(&cursor[d2], 1)] = s2;
    esrc[atomicAdd(&cursor[d3], 1)] = s3;
}

// ---------------- prep: Wn[n][k] (tf32-rounded, pad WS_STRIDE) ----------------
__global__ void prep_w(const float* __restrict__ Wrel,
                       const float* __restrict__ Wroot,
                       float* __restrict__ Wn) {
    int i = blockIdx.x * blockDim.x + threadIdx.x;
    if (i < 64 * WS_STRIDE) {
        int n = i / WS_STRIDE;
        int k = i - n * WS_STRIDE;
        float v = 0.f;
        if (k < 64)       v = Wrel [n * 64 + k];
        else if (k < 128) v = Wroot[n * 64 + (k - 64)];
        Wn[i] = to_tf32(v);
    }
}

// ---------------- gather aggregation (unchanged) ----------------
__global__ void __launch_bounds__(256)
gather_agg(const float* __restrict__ feat,
           const int* __restrict__ offs,
           const int* __restrict__ esrc,
           float* __restrict__ agg) {
    int node = blockIdx.x * (blockDim.x >> 5) + (threadIdx.x >> 5);
    if (node >= NN) return;
    int lane = threadIdx.x & 31;
    int s0 = offs[node];
    int s1 = offs[node + 1];
    const float2* f2 = reinterpret_cast<const float2*>(feat);
    float sx = 0.f, sy = 0.f;
    int j = s0;
    for (; j + 4 <= s1; j += 4) {
        int a = esrc[j], b = esrc[j + 1], c = esrc[j + 2], d = esrc[j + 3];
        float2 v0 = f2[(size_t)a * 32 + lane];
        float2 v1 = f2[(size_t)b * 32 + lane];
        float2 v2 = f2[(size_t)c * 32 + lane];
        float2 v3 = f2[(size_t)d * 32 + lane];
        sx += v0.x + v1.x + v2.x + v3.x;
        sy += v0.y + v1.y + v2.y + v3.y;
    }
    for (; j < s1; ++j) {
        float2 v = f2[(size_t)esrc[j] * 32 + lane];
        sx += v.x; sy += v.y;
    }
    reinterpret_cast<float2*>(agg)[(size_t)node * 32 + lane] = make_float2(sx, sy);
}

// ---------------- tf32 tensor-core dual-GEMM (+ fused head on FINAL) ----------
// Block: 128m x 64n, 256 threads = 8 warps, warp tile 32m x 32n.
// out = relu( agg . Wn[:,0:64] + xin . Wn[:,64:128] + bias ); FINAL: + 3-dim head.
template<bool FINAL>
__global__ void __launch_bounds__(256)
gemm_tc(const float* __restrict__ A0,    // agg [NN,64]
        const float* __restrict__ A1,    // xin [NN,64]
        const float* __restrict__ Wn,    // [64][WS_STRIDE] tf32
        const float* __restrict__ bias,  // [64]
        const float* __restrict__ Wlin,  // [3,64]  (FINAL)
        const float* __restrict__ blin,  // [3]     (FINAL)
        float* __restrict__ out) {       // [NN,64] or [NN,3]
    extern __shared__ float sm[];
    float* Bs = sm;                         // [64][132]
    float* As = Bs + 64 * WS_STRIDE;        // [128][68]
    float* bs = As + 128 * AS_STRIDE;       // [64]
    float* Wl = bs + 64;                    // [192]

    const int tid    = threadIdx.x;
    const int lane   = tid & 31;
    const int warp   = tid >> 5;
    const int warp_m = warp & 3;            // m offset *32
    const int warp_n = warp >> 2;           // n offset *32
    const int gid    = lane >> 2;           // 0..7
    const int tig    = lane & 3;            // 0..3
    const int m0     = blockIdx.x * 128;

    // stage weights (already tf32), bias, head weights
    for (int i = tid; i < 64 * WS_STRIDE; i += 256) Bs[i] = Wn[i];
    if (tid < 64) bs[tid] = bias[tid];
    if (FINAL && tid < 192) Wl[tid] = Wlin[tid];

    float acc[2][4][4];
    #pragma unroll
    for (int mt = 0; mt < 2; ++mt)
        #pragma unroll
        for (int nt = 0; nt < 4; ++nt)
            #pragma unroll
            for (int r = 0; r < 4; ++r) acc[mt][nt][r] = 0.f;

    #pragma unroll
    for (int ch = 0; ch < 2; ++ch) {
        const float* A = ch ? A1 : A0;
        if (ch) __syncthreads();             // all ch0 reads of As done
        // stage A chunk into As (tf32-rounded), 2048 float4 / 256 = 8 each
        #pragma unroll
        for (int r = 0; r < 8; ++r) {
            int idx = r * 256 + tid;
            int m   = idx >> 4;
            int q   = idx & 15;
            int gm  = m0 + m;
            float4 v = (gm < NN)
                ? *reinterpret_cast<const float4*>(A + (size_t)gm * DH + q * 4)
                : make_float4(0.f, 0.f, 0.f, 0.f);
            v.x = to_tf32(v.x);  v.y = to_tf32(v.y);
            v.z = to_tf32(v.z);  v.w = to_tf32(v.w);
            *reinterpret_cast<float4*>(As + m * AS_STRIDE + q * 4) = v;
        }
        __syncthreads();                     // As (and Bs on ch0) ready

        #pragma unroll
        for (int s = 0; s < 8; ++s) {
            unsigned a[2][4], b[4][2];
            int ac = s * 8 + tig;
            #pragma unroll
            for (int mt = 0; mt < 2; ++mt) {
                int r0 = warp_m * 32 + mt * 16 + gid;
                a[mt][0] = __float_as_uint(As[r0 * AS_STRIDE + ac]);
                a[mt][1] = __float_as_uint(As[(r0 + 8) * AS_STRIDE + ac]);
                a[mt][2] = __float_as_uint(As[r0 * AS_STRIDE + ac + 4]);
                a[mt][3] = __float_as_uint(As[(r0 + 8) * AS_STRIDE + ac + 4]);
            }
            int bk = ch * 64 + s * 8 + tig;
            #pragma unroll
            for (int nt = 0; nt < 4; ++nt) {
                int n = warp_n * 32 + nt * 8 + gid;
                b[nt][0] = __float_as_uint(Bs[n * WS_STRIDE + bk]);
                b[nt][1] = __float_as_uint(Bs[n * WS_STRIDE + bk + 4]);
            }
            #pragma unroll
            for (int mt = 0; mt < 2; ++mt)
                #pragma unroll
                for (int nt = 0; nt < 4; ++nt)
                    mma_tf32(acc[mt][nt], a[mt], b[nt]);
        }
    }

    // ---- epilogue ----
    if (!FINAL) {
        #pragma unroll
        for (int mt = 0; mt < 2; ++mt) {
            #pragma unroll
            for (int nt = 0; nt < 4; ++nt) {
                int col = warp_n * 32 + nt * 8 + 2 * tig;
                float b0 = bs[col], b1 = bs[col + 1];
                int r1 = m0 + warp_m * 32 + mt * 16 + gid;
                if (r1 < NN) {
                    float2 o = make_float2(fmaxf(acc[mt][nt][0] + b0, 0.f),
                                           fmaxf(acc[mt][nt][1] + b1, 0.f));
                    *reinterpret_cast<float2*>(out + (size_t)r1 * DH + col) = o;
                }
                int r2 = r1 + 8;
                if (r2 < NN) {
                    float2 o = make_float2(fmaxf(acc[mt][nt][2] + b0, 0.f),
                                           fmaxf(acc[mt][nt][3] + b1, 0.f));
                    *reinterpret_cast<float2*>(out + (size_t)r2 * DH + col) = o;
                }
            }
        }
    } else {
        __syncthreads();   // all k-loop reads of As done before overwrite
        #pragma unroll
        for (int mt = 0; mt < 2; ++mt) {
            #pragma unroll
            for (int nt = 0; nt < 4; ++nt) {
                int col = warp_n * 32 + nt * 8 + 2 * tig;
                float b0 = bs[col], b1 = bs[col + 1];
                int lr1 = warp_m * 32 + mt * 16 + gid;
                *reinterpret_cast<float2*>(As + lr1 * AS_STRIDE + col) =
                    make_float2(fmaxf(acc[mt][nt][0] + b0, 0.f),
                                fmaxf(acc[mt][nt][1] + b1, 0.f));
                *reinterpret_cast<float2*>(As + (lr1 + 8) * AS_STRIDE + col) =
                    make_float2(fmaxf(acc[mt][nt][2] + b0, 0.f),
                                fmaxf(acc[mt][nt][3] + b1, 0.f));
            }
        }
        __syncthreads();
        // head: 128 nodes x 3 outputs = 384 dots of length 64
        #pragma unroll
        for (int r = 0; r < 2; ++r) {
            int idx = tid + 256 * r;
            if (idx < 384) {
                int m = idx / 3;
                int o = idx - 3 * m;
                int gm = m0 + m;
                if (gm < NN) {
                    float s = blin[o];
                    const float* hrow = As + m * AS_STRIDE;
                    const float* wrow = Wl + o * 64;
                    #pragma unroll 16
                    for (int k = 0; k < 64; ++k) s += hrow[k] * wrow[k];
                    out[(size_t)gm * 3 + o] = s;
                }
            }
        }
    }
}

// ---------------- launch ----------------
extern "C" void kernel_launch(void* const* d_in, const int* in_sizes, int n_in,
                              void* d_out, int out_size) {
    const float* x      = (const float*)d_in[0];
    const void*  ei     = d_in[1];
    const float* W1_rel = (const float*)d_in[2];
    const float* b1     = (const float*)d_in[3];
    const float* W1_rt  = (const float*)d_in[4];
    const float* W2_rel = (const float*)d_in[5];
    const float* b2     = (const float*)d_in[6];
    const float* W2_rt  = (const float*)d_in[7];
    const float* W_lin  = (const float*)d_in[8];
    const float* b_lin  = (const float*)d_in[9];
    float*       out    = (float*)d_out;

    float *agg, *h1, *Wn1, *Wn2;
    int *esrc, *cnt, *offs, *cursor, *bsum;
    cudaGetSymbolAddress((void**)&agg,    g_agg);
    cudaGetSymbolAddress((void**)&h1,     g_h1);
    cudaGetSymbolAddress((void**)&Wn1,    g_Wn1);
    cudaGetSymbolAddress((void**)&Wn2,    g_Wn2);
    cudaGetSymbolAddress((void**)&esrc,   g_esrc);
    cudaGetSymbolAddress((void**)&cnt,    g_cnt);
    cudaGetSymbolAddress((void**)&offs,   g_offs);
    cudaGetSymbolAddress((void**)&cursor, g_cursor);
    cudaGetSymbolAddress((void**)&bsum,   g_bsum);

    const int smem = (64 * WS_STRIDE + 128 * AS_STRIDE + 64 + 192) * sizeof(float); // 69632 B
    cudaFuncSetAttribute(gemm_tc<false>, cudaFuncAttributeMaxDynamicSharedMemorySize, smem);
    cudaFuncSetAttribute(gemm_tc<true>,  cudaFuncAttributeMaxDynamicSharedMemorySize, smem);

    const int e4grid = (NE / 4 + 255) / 256;
    const int ngrid  = (NN + 255) / 256;
    const int ggrid  = (NN + 127) / 128;
    const int agrid  = (NN + 7) / 8;
    const int wgrid  = (64 * WS_STRIDE + 255) / 256;

    // CSR build (prep_w early so the profiled 4th launch is hist_dst)
    zero_detect<<<ngrid, 256>>>(ei, cnt);
    prep_w<<<wgrid, 256>>>(W1_rel, W1_rt, Wn1);
    prep_w<<<wgrid, 256>>>(W2_rel, W2_rt, Wn2);
    hist_dst<<<e4grid, 256>>>(ei, cnt);
    scan_blocks<<<NB, 256>>>(cnt, offs, bsum);
    scan_bsums<<<1, 128>>>(bsum);
    add_base<<<ngrid, 256>>>(offs, bsum, cursor);
    place_edges<<<e4grid, 256>>>(ei, cursor, esrc);

    // layer 1
    gather_agg<<<agrid, 256>>>(x, offs, esrc, agg);
    gemm_tc<false><<<ggrid, 256, smem>>>(agg, x, Wn1, b1, nullptr, nullptr, h1);

    // layer 2 + head
    gather_agg<<<agrid, 256>>>(h1, offs, esrc, agg);
    gemm_tc<true ><<<ggrid, 256, smem>>>(agg, h1, Wn2, b2, W_lin, b_lin, out);
}